// round 2
// baseline (speedup 1.0000x reference)
#include <cuda_runtime.h>
#include <cstddef>

// MedianFilter 7x7, exact, fp32.
// img:  [8,3,512,512] fp32   mask: [8,1,512,512] fp32
// out = concat( normalize(median7x7(clip(unnormalize(img),0,1))), mask )

#define IMG_H 512
#define IMG_W 512
#define N_PLANES 24            // 8 batches * 3 channels
#define PLANE_ELEMS (IMG_H * IMG_W)
#define IMG_ELEMS (N_PLANES * PLANE_ELEMS)     // 6,291,456
#define MASK_ELEMS (8 * PLANE_ELEMS)           // 2,097,152

#define BX 32
#define BY 8
#define TILE_W (BX + 6)        // 38
#define TILE_H (BY + 6)        // 14
#define TILE_PITCH 40          // padded row stride (floats)

__device__ __forceinline__ void ce(float& a, float& b) {
    float lo = fminf(a, b);
    b = fmaxf(a, b);
    a = lo;
}

// Place min of w[LO..HI] at w[LO] and max at w[HI]. Multiset preserved.
template <int LO, int HI>
__device__ __forceinline__ void minmax_range(float (&w)[26]) {
#pragma unroll
    for (int i = LO; i + 1 <= HI; i += 2) ce(w[i], w[i + 1]);
#pragma unroll
    for (int i = LO + 2; i <= HI; i += 2) ce(w[LO], w[i]);   // min -> w[LO]
#pragma unroll
    for (int i = LO + 1; i < HI; i += 2) ce(w[i], w[HI]);    // max -> w[HI]
}

// Median of w[0..24] -> ends in w[12]. Repeated minmax + drop both ends.
template <int S>
__device__ __forceinline__ void shrink_select(float (&w)[26]) {
    if constexpr (S < 12) {
        minmax_range<S, 24 - S>(w);
        shrink_select<S + 1>(w);
    }
}

__device__ __forceinline__ int reflect_idx(int g, int n) {
    // jnp.pad mode='reflect' (no edge repeat): -1->1, -2->2 ; n->n-2, n+1->n-3
    g = (g < 0) ? -g : g;
    g = (g >= n) ? (2 * n - 2 - g) : g;
    return g;
}

__global__ void __launch_bounds__(BX * BY)
median7_kernel(const float* __restrict__ img, float* __restrict__ out) {
    __shared__ float tile[TILE_H][TILE_PITCH];

    const int bc = blockIdx.z;          // plane index = b*3 + c
    const int c  = bc % 3;

    const float mean = (c == 0) ? 0.485f : (c == 1) ? 0.456f : 0.406f;
    const float sd   = (c == 0) ? 0.229f : (c == 1) ? 0.224f : 0.225f;

    const int x0 = blockIdx.x * BX;
    const int y0 = blockIdx.y * BY;

    const float* __restrict__ plane = img + (size_t)bc * PLANE_ELEMS;

    // ---- Cooperative tile load with unnormalize + clip ----
    const int tid = threadIdx.y * BX + threadIdx.x;
    for (int idx = tid; idx < TILE_H * TILE_W; idx += BX * BY) {
        const int r  = idx / TILE_W;
        const int cc = idx - r * TILE_W;
        const int gy = reflect_idx(y0 - 3 + r, IMG_H);
        const int gx = reflect_idx(x0 - 3 + cc, IMG_W);
        float v = fmaf(plane[gy * IMG_W + gx], sd, mean);
        tile[r][cc] = fminf(fmaxf(v, 0.0f), 1.0f);
    }
    __syncthreads();

    const int bx = threadIdx.x;
    const int by = threadIdx.y;

#define WIN(i) tile[by + ((i) / 7)][bx + ((i) % 7)]

    // ---- Forgetful selection: exact median of 49 ----
    float w[26];
#pragma unroll
    for (int i = 0; i < 26; ++i) w[i] = WIN(i);

#pragma unroll
    for (int t = 0; t < 11; ++t) {
        minmax_range<0, 25>(w);       // min->w[0], max->w[25]: both provably not the median
        w[0]  = WIN(26 + 2 * t);
        w[25] = WIN(27 + 2 * t);
    }
    minmax_range<0, 25>(w);
    w[0] = WIN(48);                   // 25 live elements in w[0..24]; 12 lows + 12 highs dropped

    shrink_select<0>(w);              // median of 25 == median of 49 -> w[12]
    const float med = w[12];

#undef WIN

    out[(size_t)bc * PLANE_ELEMS + (size_t)(y0 + by) * IMG_W + (x0 + bx)] =
        (med - mean) / sd;
}

extern "C" void kernel_launch(void* const* d_in, const int* in_sizes, int n_in,
                              void* d_out, int out_size) {
    const float* img  = (const float*)d_in[0];
    const float* mask = (const float*)d_in[1];
    float* out = (float*)d_out;

    dim3 block(BX, BY, 1);
    dim3 grid(IMG_W / BX, IMG_H / BY, N_PLANES);   // 16 x 64 x 24
    median7_kernel<<<grid, block>>>(img, out);

    // Mask passthrough (second tuple element), device-to-device, capture-legal.
    cudaMemcpyAsync(out + IMG_ELEMS, mask, (size_t)MASK_ELEMS * sizeof(float),
                    cudaMemcpyDeviceToDevice);
}

// round 4
// speedup vs baseline: 2.5673x; 2.5673x over previous
#include <cuda_runtime.h>
#include <cstddef>

// MedianFilter 7x7, exact, fp32, via compile-time-generated separable
// selection networks (sorted columns -> sorted rows -> 29-candidate merge).
// img:  [8,3,512,512] fp32   mask: [8,1,512,512] fp32
// out = concat( normalize(median7x7(clip(unnormalize(img),0,1))), mask )

#define IMG_H 512
#define IMG_W 512
#define N_PLANES 24
#define PLANE_ELEMS (IMG_H * IMG_W)
#define IMG_ELEMS (N_PLANES * PLANE_ELEMS)
#define MASK_ELEMS (8 * PLANE_ELEMS)

#define BX 32
#define BY 8
#define WOUT 4
#define OUTW (BX * WOUT)          // 128 outputs per block in x
#define TILE_W (OUTW + 6)         // 134
#define TILE_H (BY + 6)           // 14
#define TPITCH 136

// ============================================================
// Compile-time Batcher odd-even merge network generator
// ============================================================
namespace sel {

template <int CAP> struct NetT {
    short a[CAP] = {};
    short b[CAP] = {};
    int n = 0;
};

template <int CAP>
constexpr void net_add(NetT<CAP>& net, int x, int y) {
    net.a[net.n] = (short)x;
    net.b[net.n] = (short)y;
    net.n++;
}

// Batcher odd-even merge of sorted index lists A(m), B(n).
// Appends comparators to net; writes the sorted READ ORDER (m+n indices) to out.
template <int CAP>
constexpr void gen_merge(const short* A, int m, const short* B, int n,
                         short* out, NetT<CAP>& net) {
    if (m == 0) { for (int i = 0; i < n; ++i) out[i] = B[i]; return; }
    if (n == 0) { for (int i = 0; i < m; ++i) out[i] = A[i]; return; }
    if (m == 1 && n == 1) {
        net_add(net, A[0], B[0]);
        out[0] = A[0]; out[1] = B[0];
        return;
    }
    short Ae[10] = {}, Ao[10] = {}, Be[10] = {}, Bo[10] = {};
    int mae = 0, mao = 0, nbe = 0, nbo = 0;
    for (int i = 0; i < m; ++i) { if ((i & 1) == 0) Ae[mae++] = A[i]; else Ao[mao++] = A[i]; }
    for (int i = 0; i < n; ++i) { if ((i & 1) == 0) Be[nbe++] = B[i]; else Bo[nbo++] = B[i]; }
    short V[20] = {}, W[20] = {};
    gen_merge(Ae, mae, Be, nbe, V, net);
    gen_merge(Ao, mao, Bo, nbo, W, net);
    const int nv = mae + nbe, nw = mao + nbo;
    int oi = 0;
    out[oi++] = V[0];
    int i = 0;
    for (; i < nw && i + 1 < nv; ++i) {
        net_add(net, W[i], V[i + 1]);     // min stays at W[i], max at V[i+1]
        out[oi++] = W[i];
        out[oi++] = V[i + 1];
    }
    for (int j = i; j < nw; ++j) out[oi++] = W[j];
    for (int j = i + 1; j < nv; ++j) out[oi++] = V[j];
}

template <int CAP>
constexpr void gen_sort(const short* idx, int len, short* out, NetT<CAP>& net) {
    if (len == 1) { out[0] = idx[0]; return; }
    const int h = len / 2;
    short L[8] = {}, R[8] = {}, SL[8] = {}, SR[8] = {};
    for (int i = 0; i < h; ++i) L[i] = idx[i];
    for (int i = h; i < len; ++i) R[i - h] = idx[i];
    gen_sort(L, h, SL, net);
    gen_sort(R, len - h, SR, net);
    gen_merge(SL, h, SR, len - h, out, net);
}

struct Plan {
    NetT<24>  colnet;        // sort network on one 7-element column (indices 0..6)
    short     cperm[7] = {}; // read order: column[cperm[i]] = i-th smallest
    NetT<224> selnet;        // per-output: 7 row sorts + candidate merges on w[49]
    short     E[11] = {};    // sorted read order, 11-list
    short     F[18] = {};    // sorted read order, 18-list
};

constexpr Plan make_plan() {
    Plan p{};
    short base[7] = {0, 1, 2, 3, 4, 5, 6};
    gen_sort(base, 7, p.cperm, p.colnet);

    // Row sorts over w[49], row r occupies indices 7r..7r+6 (w[7r+j] = j-th
    // column's r-th smallest). rowperm[r][k] = index of k-th smallest of row r.
    short rowperm[7][7] = {};
    for (int r = 0; r < 7; ++r) {
        short idx[7] = {}, outp[7] = {};
        for (int j = 0; j < 7; ++j) idx[j] = (short)(7 * r + j);
        gen_sort(idx, 7, outp, p.selnet);
        for (int j = 0; j < 7; ++j) rowperm[r][j] = outp[j];
    }

    // Candidate chains in the both-sorted matrix: cell (r,k) is a median
    // candidate iff (r+1)(k+1) <= 25 and (7-r)(7-k) <= 25.
    short R0[3] = {}, R1[4] = {}, R2[5] = {}, R3[5] = {}, R4[5] = {}, R5[4] = {}, R6[3] = {};
    for (int j = 0; j < 3; ++j) R0[j] = rowperm[0][4 + j];
    for (int j = 0; j < 4; ++j) R1[j] = rowperm[1][3 + j];
    for (int j = 0; j < 5; ++j) R2[j] = rowperm[2][2 + j];
    for (int j = 0; j < 5; ++j) R3[j] = rowperm[3][1 + j];
    for (int j = 0; j < 5; ++j) R4[j] = rowperm[4][0 + j];
    for (int j = 0; j < 4; ++j) R5[j] = rowperm[5][0 + j];
    for (int j = 0; j < 3; ++j) R6[j] = rowperm[6][0 + j];

    short A6[6] = {}, B8[8] = {}, C10[10] = {}, E11[11] = {}, F18[18] = {};
    gen_merge(R0, 3, R6, 3, A6, p.selnet);
    gen_merge(R1, 4, R5, 4, B8, p.selnet);
    gen_merge(R2, 5, R4, 5, C10, p.selnet);
    gen_merge(A6, 6, R3, 5, E11, p.selnet);
    gen_merge(B8, 8, C10, 10, F18, p.selnet);
    for (int i = 0; i < 11; ++i) p.E[i] = E11[i];
    for (int i = 0; i < 18; ++i) p.F[i] = F18[i];
    return p;
}

constexpr Plan PLAN = make_plan();

static_assert(PLAN.colnet.n <= 24, "colnet overflow");
static_assert(PLAN.selnet.n <= 224, "selnet overflow");

// ---- compile-time verification ----

// sort7 network: exhaustive 0/1 check (validates the whole generator).
constexpr bool check_sort7() {
    for (int mask = 0; mask < 128; ++mask) {
        int v[7] = {};
        for (int i = 0; i < 7; ++i) v[i] = (mask >> i) & 1;
        for (int k = 0; k < PLAN.colnet.n; ++k) {
            const int x = v[PLAN.colnet.a[k]], y = v[PLAN.colnet.b[k]];
            v[PLAN.colnet.a[k]] = x < y ? x : y;
            v[PLAN.colnet.b[k]] = x < y ? y : x;
        }
        for (int i = 0; i + 1 < 7; ++i)
            if (v[PLAN.cperm[i]] > v[PLAN.cperm[i + 1]]) return false;
    }
    return true;
}
static_assert(check_sort7(), "sort7 network invalid");

// Selection stage: 0/1 principle on both-sorted inputs (h0<=...<=h6 ones per
// column). Circuit is monotone, so checking the boundary totals 24 (->0) and
// 25 (->1) proves correctness for all inputs.
constexpr bool check_select() {
    for (int h0 = 0; h0 <= 7; ++h0)
    for (int h1 = h0; h1 <= 7; ++h1)
    for (int h2 = h1; h2 <= 7; ++h2)
    for (int h3 = h2; h3 <= 7; ++h3)
    for (int h4 = h3; h4 <= 7; ++h4)
    for (int h5 = h4; h5 <= 7; ++h5)
    for (int h6 = h5; h6 <= 7; ++h6) {
        const int tot = h0 + h1 + h2 + h3 + h4 + h5 + h6;
        if (tot != 24 && tot != 25) continue;
        const int h[7] = {h0, h1, h2, h3, h4, h5, h6};
        int w[49] = {};
        for (int r = 0; r < 7; ++r)
            for (int c = 0; c < 7; ++c)
                w[7 * r + c] = (r >= 7 - h[c]) ? 1 : 0;
        for (int k = 0; k < PLAN.selnet.n; ++k) {
            const int x = w[PLAN.selnet.a[k]], y = w[PLAN.selnet.b[k]];
            w[PLAN.selnet.a[k]] = x < y ? x : y;
            w[PLAN.selnet.b[k]] = x < y ? y : x;
        }
        // rank-15 (1-based) of E(11) ∪ F(18)
        int res = w[PLAN.F[14]];
        for (int i = 1; i <= 11; ++i) {
            const int t1 = w[PLAN.E[i - 1]], t2 = w[PLAN.F[14 - i]];
            const int mx = t1 > t2 ? t1 : t2;
            res = res < mx ? res : mx;
        }
        if (res != (tot >= 25 ? 1 : 0)) return false;
    }
    return true;
}
static_assert(check_select(), "median selection network invalid");

}  // namespace sel

// ============================================================
// Device side
// ============================================================

__device__ __forceinline__ void ce(float& x, float& y) {
    const float lo = fminf(x, y);
    y = fmaxf(x, y);
    x = lo;
}

template <int K>
__device__ __forceinline__ void apply_col(float (&v)[7]) {
    if constexpr (K < sel::PLAN.colnet.n) {
        constexpr int ia = sel::PLAN.colnet.a[K];
        constexpr int ib = sel::PLAN.colnet.b[K];
        ce(v[ia], v[ib]);
        apply_col<K + 1>(v);
    }
}

template <int K>
__device__ __forceinline__ void apply_sel(float (&w)[49]) {
    if constexpr (K < sel::PLAN.selnet.n) {
        constexpr int ia = sel::PLAN.selnet.a[K];
        constexpr int ib = sel::PLAN.selnet.b[K];
        ce(w[ia], w[ib]);
        apply_sel<K + 1>(w);
    }
}

template <int I, int O>
__device__ __forceinline__ void build_rows(float (&w)[49], const float (&c)[10][7]) {
    if constexpr (I < 49) {
        constexpr int r = I / 7;
        constexpr int j = I % 7;
        constexpr int cp = sel::PLAN.cperm[r];
        w[I] = c[O + j][cp];
        build_rows<I + 1, O>(w, c);
    }
}

template <int I>
__device__ __forceinline__ void rank_terms(float (&t)[12], const float (&w)[49]) {
    if constexpr (I <= 11) {
        constexpr int e = sel::PLAN.E[I - 1];
        constexpr int f = sel::PLAN.F[14 - I];
        t[I] = fmaxf(w[e], w[f]);
        rank_terms<I + 1>(t, w);
    }
}

template <int O>
__device__ __forceinline__ float do_out(const float (&c)[10][7]) {
    float w[49];
    build_rows<0, O>(w, c);
    apply_sel<0>(w);
    float t[12];
    {
        constexpr int f14 = sel::PLAN.F[14];
        t[0] = w[f14];
    }
    rank_terms<1>(t, w);
#pragma unroll
    for (int k = 0; k < 6; ++k) t[k] = fminf(t[k], t[k + 6]);
#pragma unroll
    for (int k = 0; k < 3; ++k) t[k] = fminf(t[k], t[k + 3]);
    return fminf(t[0], fminf(t[1], t[2]));
}

__device__ __forceinline__ int reflect_idx(int g, int n) {
    g = (g < 0) ? -g : g;
    g = (g >= n) ? (2 * n - 2 - g) : g;
    return g;
}

__global__ void __launch_bounds__(BX * BY)
median7_kernel(const float* __restrict__ img, float* __restrict__ out) {
    __shared__ float tile[TILE_H][TPITCH];

    const int bc = blockIdx.z;
    const int ch = bc % 3;
    const float mean   = (ch == 0) ? 0.485f : (ch == 1) ? 0.456f : 0.406f;
    const float sd     = (ch == 0) ? 0.229f : (ch == 1) ? 0.224f : 0.225f;
    const float inv_sd = (ch == 0) ? (1.0f / 0.229f) : (ch == 1) ? (1.0f / 0.224f) : (1.0f / 0.225f);

    const int x0 = blockIdx.x * OUTW;
    const int y0 = blockIdx.y * BY;
    const float* __restrict__ plane = img + (size_t)bc * PLANE_ELEMS;

    const int tid = threadIdx.y * BX + threadIdx.x;
    for (int idx = tid; idx < TILE_H * TILE_W; idx += BX * BY) {
        const int r  = idx / TILE_W;
        const int cc = idx - r * TILE_W;
        const int gy = reflect_idx(y0 - 3 + r, IMG_H);
        const int gx = reflect_idx(x0 - 3 + cc, IMG_W);
        const float v = fmaf(plane[gy * IMG_W + gx], sd, mean);
        tile[r][cc] = fminf(fmaxf(v, 0.0f), 1.0f);
    }
    __syncthreads();

    // 10 columns of 7, sorted once, shared by the 4 output windows.
    float c[10][7];
    const int lx = threadIdx.x * WOUT;
    const int ty = threadIdx.y;
#pragma unroll
    for (int x = 0; x < 10; ++x) {
#pragma unroll
        for (int i = 0; i < 7; ++i) c[x][i] = tile[ty + i][lx + x];
        apply_col<0>(c[x]);
    }

    float4 res;
    res.x = (do_out<0>(c) - mean) * inv_sd;
    res.y = (do_out<1>(c) - mean) * inv_sd;
    res.z = (do_out<2>(c) - mean) * inv_sd;
    res.w = (do_out<3>(c) - mean) * inv_sd;

    float* op = out + (size_t)bc * PLANE_ELEMS + (size_t)(y0 + ty) * IMG_W + (x0 + lx);
    *reinterpret_cast<float4*>(op) = res;
}

extern "C" void kernel_launch(void* const* d_in, const int* in_sizes, int n_in,
                              void* d_out, int out_size) {
    const float* img  = (const float*)d_in[0];
    const float* mask = (const float*)d_in[1];
    float* out = (float*)d_out;

    dim3 block(BX, BY, 1);
    dim3 grid(IMG_W / OUTW, IMG_H / BY, N_PLANES);   // 4 x 64 x 24
    median7_kernel<<<grid, block>>>(img, out);

    cudaMemcpyAsync(out + IMG_ELEMS, mask, (size_t)MASK_ELEMS * sizeof(float),
                    cudaMemcpyDeviceToDevice);
}

// round 6
// speedup vs baseline: 3.0709x; 1.1961x over previous
#include <cuda_runtime.h>
#include <cstddef>

// MedianFilter 7x7, exact, fp32. Sorted columns staged in SHARED MEMORY
// (sorted once per row-window, shared by all 128 outputs of that row),
// then per-output both-sorted-matrix selection in registers.
// img:  [8,3,512,512] fp32   mask: [8,1,512,512] fp32
// out = concat( normalize(median7x7(clip(unnormalize(img),0,1))), mask )

#define IMG_H 512
#define IMG_W 512
#define N_PLANES 24
#define PLANE_ELEMS (IMG_H * IMG_W)
#define IMG_ELEMS (N_PLANES * PLANE_ELEMS)
#define MASK_ELEMS (8 * PLANE_ELEMS)

#define BX 32
#define BY 8
#define WOUT 4
#define OUTW (BX * WOUT)          // 128 outputs per block in x
#define TILE_W (OUTW + 6)         // 134
#define TILE_H (BY + 6)           // 14
#define TPITCH 136

// ============================================================
// Compile-time Batcher odd-even merge network generator
// ============================================================
namespace sel {

template <int CAP> struct NetT {
    short a[CAP] = {};
    short b[CAP] = {};
    int n = 0;
};

template <int CAP>
constexpr void net_add(NetT<CAP>& net, int x, int y) {
    net.a[net.n] = (short)x;
    net.b[net.n] = (short)y;
    net.n++;
}

// Batcher odd-even merge of sorted index lists A(m), B(n).
// Appends comparators to net; writes the sorted READ ORDER (m+n indices) to out.
template <int CAP>
constexpr void gen_merge(const short* A, int m, const short* B, int n,
                         short* out, NetT<CAP>& net) {
    if (m == 0) { for (int i = 0; i < n; ++i) out[i] = B[i]; return; }
    if (n == 0) { for (int i = 0; i < m; ++i) out[i] = A[i]; return; }
    if (m == 1 && n == 1) {
        net_add(net, A[0], B[0]);
        out[0] = A[0]; out[1] = B[0];
        return;
    }
    short Ae[10] = {}, Ao[10] = {}, Be[10] = {}, Bo[10] = {};
    int mae = 0, mao = 0, nbe = 0, nbo = 0;
    for (int i = 0; i < m; ++i) { if ((i & 1) == 0) Ae[mae++] = A[i]; else Ao[mao++] = A[i]; }
    for (int i = 0; i < n; ++i) { if ((i & 1) == 0) Be[nbe++] = B[i]; else Bo[nbo++] = B[i]; }
    short V[20] = {}, W[20] = {};
    gen_merge(Ae, mae, Be, nbe, V, net);
    gen_merge(Ao, mao, Bo, nbo, W, net);
    const int nv = mae + nbe, nw = mao + nbo;
    int oi = 0;
    out[oi++] = V[0];
    int i = 0;
    for (; i < nw && i + 1 < nv; ++i) {
        net_add(net, W[i], V[i + 1]);     // min stays at W[i], max at V[i+1]
        out[oi++] = W[i];
        out[oi++] = V[i + 1];
    }
    for (int j = i; j < nw; ++j) out[oi++] = W[j];
    for (int j = i + 1; j < nv; ++j) out[oi++] = V[j];
}

template <int CAP>
constexpr void gen_sort(const short* idx, int len, short* out, NetT<CAP>& net) {
    if (len == 1) { out[0] = idx[0]; return; }
    const int h = len / 2;
    short L[8] = {}, R[8] = {}, SL[8] = {}, SR[8] = {};
    for (int i = 0; i < h; ++i) L[i] = idx[i];
    for (int i = h; i < len; ++i) R[i - h] = idx[i];
    gen_sort(L, h, SL, net);
    gen_sort(R, len - h, SR, net);
    gen_merge(SL, h, SR, len - h, out, net);
}

struct Plan {
    NetT<24>  colnet;        // sort network on one 7-element column (indices 0..6)
    short     cperm[7] = {}; // read order: column[cperm[i]] = i-th smallest
    NetT<224> selnet;        // per-output: 7 row sorts + candidate merges on w[49]
    short     E[11] = {};    // sorted read order, 11-list
    short     F[18] = {};    // sorted read order, 18-list
};

constexpr Plan make_plan() {
    Plan p{};
    short base[7] = {0, 1, 2, 3, 4, 5, 6};
    gen_sort(base, 7, p.cperm, p.colnet);

    // Row sorts over w[49]; w[7r+j] = j-th window column's r-th smallest.
    short rowperm[7][7] = {};
    for (int r = 0; r < 7; ++r) {
        short idx[7] = {}, outp[7] = {};
        for (int j = 0; j < 7; ++j) idx[j] = (short)(7 * r + j);
        gen_sort(idx, 7, outp, p.selnet);
        for (int j = 0; j < 7; ++j) rowperm[r][j] = outp[j];
    }

    // Candidate chains in the both-sorted matrix: cell (r,k) is a median
    // candidate iff (r+1)(k+1) <= 25 and (7-r)(7-k) <= 25.
    short R0[3] = {}, R1[4] = {}, R2[5] = {}, R3[5] = {}, R4[5] = {}, R5[4] = {}, R6[3] = {};
    for (int j = 0; j < 3; ++j) R0[j] = rowperm[0][4 + j];
    for (int j = 0; j < 4; ++j) R1[j] = rowperm[1][3 + j];
    for (int j = 0; j < 5; ++j) R2[j] = rowperm[2][2 + j];
    for (int j = 0; j < 5; ++j) R3[j] = rowperm[3][1 + j];
    for (int j = 0; j < 5; ++j) R4[j] = rowperm[4][0 + j];
    for (int j = 0; j < 4; ++j) R5[j] = rowperm[5][0 + j];
    for (int j = 0; j < 3; ++j) R6[j] = rowperm[6][0 + j];

    short A6[6] = {}, B8[8] = {}, C10[10] = {}, E11[11] = {}, F18[18] = {};
    gen_merge(R0, 3, R6, 3, A6, p.selnet);
    gen_merge(R1, 4, R5, 4, B8, p.selnet);
    gen_merge(R2, 5, R4, 5, C10, p.selnet);
    gen_merge(A6, 6, R3, 5, E11, p.selnet);
    gen_merge(B8, 8, C10, 10, F18, p.selnet);
    for (int i = 0; i < 11; ++i) p.E[i] = E11[i];
    for (int i = 0; i < 18; ++i) p.F[i] = F18[i];
    return p;
}

constexpr Plan PLAN = make_plan();

static_assert(PLAN.colnet.n <= 24, "colnet overflow");
static_assert(PLAN.selnet.n <= 224, "selnet overflow");

// Integral constexpr: folds to an immediate in device code.
constexpr int F14 = PLAN.F[14];

// ---- compile-time verification ----

// sort7 network: exhaustive 0/1 check (validates the whole generator).
constexpr bool check_sort7() {
    for (int mask = 0; mask < 128; ++mask) {
        int v[7] = {};
        for (int i = 0; i < 7; ++i) v[i] = (mask >> i) & 1;
        for (int k = 0; k < PLAN.colnet.n; ++k) {
            const int x = v[PLAN.colnet.a[k]], y = v[PLAN.colnet.b[k]];
            v[PLAN.colnet.a[k]] = x < y ? x : y;
            v[PLAN.colnet.b[k]] = x < y ? y : x;
        }
        for (int i = 0; i + 1 < 7; ++i)
            if (v[PLAN.cperm[i]] > v[PLAN.cperm[i + 1]]) return false;
    }
    return true;
}
static_assert(check_sort7(), "sort7 network invalid");

// Selection stage: 0/1 principle on both-sorted inputs. The circuit is
// monotone; checking boundary totals 24 (->0) and 25 (->1) proves all inputs.
constexpr bool check_select() {
    for (int h0 = 0; h0 <= 7; ++h0)
    for (int h1 = h0; h1 <= 7; ++h1)
    for (int h2 = h1; h2 <= 7; ++h2)
    for (int h3 = h2; h3 <= 7; ++h3)
    for (int h4 = h3; h4 <= 7; ++h4)
    for (int h5 = h4; h5 <= 7; ++h5)
    for (int h6 = h5; h6 <= 7; ++h6) {
        const int tot = h0 + h1 + h2 + h3 + h4 + h5 + h6;
        if (tot != 24 && tot != 25) continue;
        const int h[7] = {h0, h1, h2, h3, h4, h5, h6};
        int w[49] = {};
        for (int r = 0; r < 7; ++r)
            for (int c = 0; c < 7; ++c)
                w[7 * r + c] = (r >= 7 - h[c]) ? 1 : 0;
        for (int k = 0; k < PLAN.selnet.n; ++k) {
            const int x = w[PLAN.selnet.a[k]], y = w[PLAN.selnet.b[k]];
            w[PLAN.selnet.a[k]] = x < y ? x : y;
            w[PLAN.selnet.b[k]] = x < y ? y : x;
        }
        int res = w[F14];
        for (int i = 1; i <= 11; ++i) {
            const int t1 = w[PLAN.E[i - 1]], t2 = w[PLAN.F[14 - i]];
            const int mx = t1 > t2 ? t1 : t2;
            res = res < mx ? res : mx;
        }
        if (res != (tot >= 25 ? 1 : 0)) return false;
    }
    return true;
}
static_assert(check_select(), "median selection network invalid");

}  // namespace sel

// ============================================================
// Device side
// ============================================================

__device__ __forceinline__ void ce(float& x, float& y) {
    const float lo = fminf(x, y);
    y = fmaxf(x, y);
    x = lo;
}

template <int K>
__device__ __forceinline__ void apply_col(float (&v)[7]) {
    if constexpr (K < sel::PLAN.colnet.n) {
        constexpr int ia = sel::PLAN.colnet.a[K];
        constexpr int ib = sel::PLAN.colnet.b[K];
        ce(v[ia], v[ib]);
        apply_col<K + 1>(v);
    }
}

template <int K>
__device__ __forceinline__ void apply_sel(float (&w)[49]) {
    if constexpr (K < sel::PLAN.selnet.n) {
        constexpr int ia = sel::PLAN.selnet.a[K];
        constexpr int ib = sel::PLAN.selnet.b[K];
        ce(w[ia], w[ib]);
        apply_sel<K + 1>(w);
    }
}

template <int I>
__device__ __forceinline__ void rank_terms(float (&t)[12], const float (&w)[49]) {
    if constexpr (I <= 11) {
        constexpr int e = sel::PLAN.E[I - 1];
        constexpr int f = sel::PLAN.F[14 - I];
        t[I] = fmaxf(w[e], w[f]);
        rank_terms<I + 1>(t, w);
    }
}

// Store sorted column to shared in rank order; cperm index made constexpr.
template <int R>
__device__ __forceinline__ void store_sorted(const float (&v)[7],
                                             float (*scol)[BY][TPITCH],
                                             int ty, int col) {
    if constexpr (R < 7) {
        constexpr int cp = sel::PLAN.cperm[R];
        scol[R][ty][col] = v[cp];
        store_sorted<R + 1>(v, scol, ty, col);
    }
}

__device__ __forceinline__ int reflect_idx(int g, int n) {
    g = (g < 0) ? -g : g;
    g = (g >= n) ? (2 * n - 2 - g) : g;
    return g;
}

__global__ void __launch_bounds__(BX * BY, 3)
median7_kernel(const float* __restrict__ img, float* __restrict__ out) {
    __shared__ float tile[TILE_H][TPITCH];           // 7.6 KB
    __shared__ float scol[7][BY][TPITCH];            // 30.5 KB: sorted columns

    const int bc = blockIdx.z;
    const int ch = bc % 3;
    const float mean   = (ch == 0) ? 0.485f : (ch == 1) ? 0.456f : 0.406f;
    const float sd     = (ch == 0) ? 0.229f : (ch == 1) ? 0.224f : 0.225f;
    const float inv_sd = (ch == 0) ? (1.0f / 0.229f) : (ch == 1) ? (1.0f / 0.224f) : (1.0f / 0.225f);

    const int x0 = blockIdx.x * OUTW;
    const int y0 = blockIdx.y * BY;
    const float* __restrict__ plane = img + (size_t)bc * PLANE_ELEMS;

    const int tx = threadIdx.x;
    const int ty = threadIdx.y;
    const int tid = ty * BX + tx;

    // ---- Phase 1: load + unnormalize + clip into shared tile ----
    for (int idx = tid; idx < TILE_H * TILE_W; idx += BX * BY) {
        const int r  = idx / TILE_W;
        const int cc = idx - r * TILE_W;
        const int gy = reflect_idx(y0 - 3 + r, IMG_H);
        const int gx = reflect_idx(x0 - 3 + cc, IMG_W);
        const float v = fmaf(plane[gy * IMG_W + gx], sd, mean);
        tile[r][cc] = fminf(fmaxf(v, 0.0f), 1.0f);
    }
    __syncthreads();

    // ---- Phase 2: sort every column of every row-window once; store sorted ----
    // Thread (tx,ty) sorts columns tx, tx+32, ... for its row-window [ty, ty+6].
#pragma unroll
    for (int k = 0; k < 5; ++k) {
        const int col = tx + 32 * k;
        if (col < TILE_W) {
            float v[7];
#pragma unroll
            for (int i = 0; i < 7; ++i) v[i] = tile[ty + i][col];
            apply_col<0>(v);
            store_sorted<0>(v, scol, ty, col);
        }
    }
    __syncthreads();

    // ---- Phase 3: 4 outputs per thread, strided by 32 (conflict-free LDS) ----
#pragma unroll
    for (int o = 0; o < WOUT; ++o) {
        const int base = tx + 32 * o;       // window's leftmost local column
        float w[49];
#pragma unroll
        for (int r = 0; r < 7; ++r)
#pragma unroll
            for (int j = 0; j < 7; ++j)
                w[7 * r + j] = scol[r][ty][base + j];

        apply_sel<0>(w);

        float t[12];
        t[0] = w[sel::F14];
        rank_terms<1>(t, w);
#pragma unroll
        for (int k = 0; k < 6; ++k) t[k] = fminf(t[k], t[k + 6]);
#pragma unroll
        for (int k = 0; k < 3; ++k) t[k] = fminf(t[k], t[k + 3]);
        const float med = fminf(t[0], fminf(t[1], t[2]));

        out[(size_t)bc * PLANE_ELEMS + (size_t)(y0 + ty) * IMG_W + (x0 + base)] =
            (med - mean) * inv_sd;
    }
}

extern "C" void kernel_launch(void* const* d_in, const int* in_sizes, int n_in,
                              void* d_out, int out_size) {
    const float* img  = (const float*)d_in[0];
    const float* mask = (const float*)d_in[1];
    float* out = (float*)d_out;

    dim3 block(BX, BY, 1);
    dim3 grid(IMG_W / OUTW, IMG_H / BY, N_PLANES);   // 4 x 64 x 24
    median7_kernel<<<grid, block>>>(img, out);

    cudaMemcpyAsync(out + IMG_ELEMS, mask, (size_t)MASK_ELEMS * sizeof(float),
                    cudaMemcpyDeviceToDevice);
}

// round 8
// speedup vs baseline: 3.0777x; 1.0022x over previous
#include <cuda_runtime.h>
#include <cstddef>

// MedianFilter 7x7, exact, fp32. Sorted columns staged in SHARED MEMORY,
// per-output both-sorted-matrix selection in registers, and compile-time
// dead-comparator elimination on the selection network (only the 29 wires
// the rank formula reads are kept live; verified by 0/1 principle at
// compile time on the PRUNED network).
// img:  [8,3,512,512] fp32   mask: [8,1,512,512] fp32
// out = concat( normalize(median7x7(clip(unnormalize(img),0,1))), mask )

#define IMG_H 512
#define IMG_W 512
#define N_PLANES 24
#define PLANE_ELEMS (IMG_H * IMG_W)
#define IMG_ELEMS (N_PLANES * PLANE_ELEMS)
#define MASK_ELEMS (8 * PLANE_ELEMS)

#define BX 32
#define BY 8
#define WOUT 4
#define OUTW (BX * WOUT)          // 128 outputs per block in x
#define TILE_W (OUTW + 6)         // 134
#define TILE_H (BY + 6)           // 14
#define TPITCH 136

// ============================================================
// Compile-time Batcher odd-even merge network generator + DCE
// ============================================================
namespace sel {

template <int CAP> struct NetT {
    short a[CAP] = {};
    short b[CAP] = {};
    int n = 0;
};

template <int CAP>
constexpr void net_add(NetT<CAP>& net, int x, int y) {
    net.a[net.n] = (short)x;
    net.b[net.n] = (short)y;
    net.n++;
}

// Batcher odd-even merge of sorted index lists A(m), B(n).
// Appends comparators to net; writes the sorted READ ORDER (m+n indices) to out.
template <int CAP>
constexpr void gen_merge(const short* A, int m, const short* B, int n,
                         short* out, NetT<CAP>& net) {
    if (m == 0) { for (int i = 0; i < n; ++i) out[i] = B[i]; return; }
    if (n == 0) { for (int i = 0; i < m; ++i) out[i] = A[i]; return; }
    if (m == 1 && n == 1) {
        net_add(net, A[0], B[0]);
        out[0] = A[0]; out[1] = B[0];
        return;
    }
    short Ae[10] = {}, Ao[10] = {}, Be[10] = {}, Bo[10] = {};
    int mae = 0, mao = 0, nbe = 0, nbo = 0;
    for (int i = 0; i < m; ++i) { if ((i & 1) == 0) Ae[mae++] = A[i]; else Ao[mao++] = A[i]; }
    for (int i = 0; i < n; ++i) { if ((i & 1) == 0) Be[nbe++] = B[i]; else Bo[nbo++] = B[i]; }
    short V[20] = {}, W[20] = {};
    gen_merge(Ae, mae, Be, nbe, V, net);
    gen_merge(Ao, mao, Bo, nbo, W, net);
    const int nv = mae + nbe, nw = mao + nbo;
    int oi = 0;
    out[oi++] = V[0];
    int i = 0;
    for (; i < nw && i + 1 < nv; ++i) {
        net_add(net, W[i], V[i + 1]);     // min stays at W[i], max at V[i+1]
        out[oi++] = W[i];
        out[oi++] = V[i + 1];
    }
    for (int j = i; j < nw; ++j) out[oi++] = W[j];
    for (int j = i + 1; j < nv; ++j) out[oi++] = V[j];
}

template <int CAP>
constexpr void gen_sort(const short* idx, int len, short* out, NetT<CAP>& net) {
    if (len == 1) { out[0] = idx[0]; return; }
    const int h = len / 2;
    short L[8] = {}, R[8] = {}, SL[8] = {}, SR[8] = {};
    for (int i = 0; i < h; ++i) L[i] = idx[i];
    for (int i = h; i < len; ++i) R[i - h] = idx[i];
    gen_sort(L, h, SL, net);
    gen_sort(R, len - h, SR, net);
    gen_merge(SL, h, SR, len - h, out, net);
}

struct Plan {
    NetT<24>  colnet;        // sort network on one 7-element column (indices 0..6)
    short     cperm[7] = {}; // read order: column[cperm[i]] = i-th smallest
    NetT<224> selnet;        // per-output network on w[49]
    short     E[11] = {};    // sorted read order, 11-list
    short     F[18] = {};    // sorted read order, 18-list
};

constexpr Plan make_plan_raw() {
    Plan p{};
    short base[7] = {0, 1, 2, 3, 4, 5, 6};
    gen_sort(base, 7, p.cperm, p.colnet);

    // Row sorts over w[49]; w[7r+j] = j-th window column's r-th smallest.
    short rowperm[7][7] = {};
    for (int r = 0; r < 7; ++r) {
        short idx[7] = {}, outp[7] = {};
        for (int j = 0; j < 7; ++j) idx[j] = (short)(7 * r + j);
        gen_sort(idx, 7, outp, p.selnet);
        for (int j = 0; j < 7; ++j) rowperm[r][j] = outp[j];
    }

    // Candidate chains in the both-sorted matrix: cell (r,k) is a median
    // candidate iff (r+1)(k+1) <= 25 and (7-r)(7-k) <= 25.
    short R0[3] = {}, R1[4] = {}, R2[5] = {}, R3[5] = {}, R4[5] = {}, R5[4] = {}, R6[3] = {};
    for (int j = 0; j < 3; ++j) R0[j] = rowperm[0][4 + j];
    for (int j = 0; j < 4; ++j) R1[j] = rowperm[1][3 + j];
    for (int j = 0; j < 5; ++j) R2[j] = rowperm[2][2 + j];
    for (int j = 0; j < 5; ++j) R3[j] = rowperm[3][1 + j];
    for (int j = 0; j < 5; ++j) R4[j] = rowperm[4][0 + j];
    for (int j = 0; j < 4; ++j) R5[j] = rowperm[5][0 + j];
    for (int j = 0; j < 3; ++j) R6[j] = rowperm[6][0 + j];

    short A6[6] = {}, B8[8] = {}, C10[10] = {}, E11[11] = {}, F18[18] = {};
    gen_merge(R0, 3, R6, 3, A6, p.selnet);
    gen_merge(R1, 4, R5, 4, B8, p.selnet);
    gen_merge(R2, 5, R4, 5, C10, p.selnet);
    gen_merge(A6, 6, R3, 5, E11, p.selnet);
    gen_merge(B8, 8, C10, 10, F18, p.selnet);
    for (int i = 0; i < 11; ++i) p.E[i] = E11[i];
    for (int i = 0; i < 18; ++i) p.F[i] = F18[i];
    return p;
}

// Backward dead-comparator elimination. Only wires read downstream are live:
// E[0..10] and F[3..14]. A comparator with both output wires dead is removed;
// a kept comparator makes both its wires live. The pruned network is
// re-verified end-to-end by check_select below.
constexpr Plan prune_plan(Plan p) {
    bool live[49] = {};
    for (int i = 0; i < 11; ++i) live[p.E[i]] = true;
    for (int i = 3; i <= 14; ++i) live[p.F[i]] = true;

    short ra[224] = {}, rb[224] = {};
    int rn = 0;
    for (int k = p.selnet.n - 1; k >= 0; --k) {
        const int a = p.selnet.a[k], b = p.selnet.b[k];
        if (live[a] || live[b]) {
            ra[rn] = (short)a; rb[rn] = (short)b; rn++;
            live[a] = true; live[b] = true;
        }
    }
    NetT<224> nn{};
    for (int k = rn - 1; k >= 0; --k) net_add(nn, ra[k], rb[k]);
    p.selnet = nn;
    return p;
}

constexpr Plan PLAN = prune_plan(make_plan_raw());

static_assert(PLAN.colnet.n <= 24, "colnet overflow");
static_assert(PLAN.selnet.n <= 224, "selnet overflow");

// Integral constexpr: folds to an immediate in device code.
constexpr int F14 = PLAN.F[14];

// ---- compile-time verification (runs on the PRUNED network) ----

constexpr bool check_sort7() {
    for (int mask = 0; mask < 128; ++mask) {
        int v[7] = {};
        for (int i = 0; i < 7; ++i) v[i] = (mask >> i) & 1;
        for (int k = 0; k < PLAN.colnet.n; ++k) {
            const int x = v[PLAN.colnet.a[k]], y = v[PLAN.colnet.b[k]];
            v[PLAN.colnet.a[k]] = x < y ? x : y;
            v[PLAN.colnet.b[k]] = x < y ? y : x;
        }
        for (int i = 0; i + 1 < 7; ++i)
            if (v[PLAN.cperm[i]] > v[PLAN.cperm[i + 1]]) return false;
    }
    return true;
}
static_assert(check_sort7(), "sort7 network invalid");

// 0/1 principle on both-sorted inputs; the full circuit (pruned selnet +
// rank formula) is monotone, so boundary totals 24 (->0) and 25 (->1)
// prove correctness for all inputs.
constexpr bool check_select() {
    for (int h0 = 0; h0 <= 7; ++h0)
    for (int h1 = h0; h1 <= 7; ++h1)
    for (int h2 = h1; h2 <= 7; ++h2)
    for (int h3 = h2; h3 <= 7; ++h3)
    for (int h4 = h3; h4 <= 7; ++h4)
    for (int h5 = h4; h5 <= 7; ++h5)
    for (int h6 = h5; h6 <= 7; ++h6) {
        const int tot = h0 + h1 + h2 + h3 + h4 + h5 + h6;
        if (tot != 24 && tot != 25) continue;
        const int h[7] = {h0, h1, h2, h3, h4, h5, h6};
        int w[49] = {};
        for (int r = 0; r < 7; ++r)
            for (int c = 0; c < 7; ++c)
                w[7 * r + c] = (r >= 7 - h[c]) ? 1 : 0;
        for (int k = 0; k < PLAN.selnet.n; ++k) {
            const int x = w[PLAN.selnet.a[k]], y = w[PLAN.selnet.b[k]];
            w[PLAN.selnet.a[k]] = x < y ? x : y;
            w[PLAN.selnet.b[k]] = x < y ? y : x;
        }
        int res = w[F14];
        for (int i = 1; i <= 11; ++i) {
            const int t1 = w[PLAN.E[i - 1]], t2 = w[PLAN.F[14 - i]];
            const int mx = t1 > t2 ? t1 : t2;
            res = res < mx ? res : mx;
        }
        if (res != (tot >= 25 ? 1 : 0)) return false;
    }
    return true;
}
static_assert(check_select(), "median selection network invalid");

}  // namespace sel

// ============================================================
// Device side
// ============================================================

__device__ __forceinline__ void ce(float& x, float& y) {
    const float lo = fminf(x, y);
    y = fmaxf(x, y);
    x = lo;
}

template <int K>
__device__ __forceinline__ void apply_col(float (&v)[7]) {
    if constexpr (K < sel::PLAN.colnet.n) {
        constexpr int ia = sel::PLAN.colnet.a[K];
        constexpr int ib = sel::PLAN.colnet.b[K];
        ce(v[ia], v[ib]);
        apply_col<K + 1>(v);
    }
}

template <int K>
__device__ __forceinline__ void apply_sel(float (&w)[49]) {
    if constexpr (K < sel::PLAN.selnet.n) {
        constexpr int ia = sel::PLAN.selnet.a[K];
        constexpr int ib = sel::PLAN.selnet.b[K];
        ce(w[ia], w[ib]);
        apply_sel<K + 1>(w);
    }
}

template <int I>
__device__ __forceinline__ void rank_terms(float (&t)[12], const float (&w)[49]) {
    if constexpr (I <= 11) {
        constexpr int e = sel::PLAN.E[I - 1];
        constexpr int f = sel::PLAN.F[14 - I];
        t[I] = fmaxf(w[e], w[f]);
        rank_terms<I + 1>(t, w);
    }
}

// Store sorted column to shared in rank order; cperm index made constexpr.
template <int R>
__device__ __forceinline__ void store_sorted(const float (&v)[7],
                                             float (*scol)[BY][TPITCH],
                                             int ty, int col) {
    if constexpr (R < 7) {
        constexpr int cp = sel::PLAN.cperm[R];
        scol[R][ty][col] = v[cp];
        store_sorted<R + 1>(v, scol, ty, col);
    }
}

__device__ __forceinline__ int reflect_idx(int g, int n) {
    g = (g < 0) ? -g : g;
    g = (g >= n) ? (2 * n - 2 - g) : g;
    return g;
}

__global__ void __launch_bounds__(BX * BY, 3)
median7_kernel(const float* __restrict__ img, float* __restrict__ out) {
    __shared__ float tile[TILE_H][TPITCH];           // 7.6 KB
    __shared__ float scol[7][BY][TPITCH];            // 30.5 KB: sorted columns

    const int bc = blockIdx.z;
    const int ch = bc % 3;
    const float mean   = (ch == 0) ? 0.485f : (ch == 1) ? 0.456f : 0.406f;
    const float sd     = (ch == 0) ? 0.229f : (ch == 1) ? 0.224f : 0.225f;
    const float inv_sd = (ch == 0) ? (1.0f / 0.229f) : (ch == 1) ? (1.0f / 0.224f) : (1.0f / 0.225f);

    const int x0 = blockIdx.x * OUTW;
    const int y0 = blockIdx.y * BY;
    const float* __restrict__ plane = img + (size_t)bc * PLANE_ELEMS;

    const int tx = threadIdx.x;
    const int ty = threadIdx.y;
    const int tid = ty * BX + tx;

    // ---- Phase 1: load + unnormalize + clip into shared tile ----
    for (int idx = tid; idx < TILE_H * TILE_W; idx += BX * BY) {
        const int r  = idx / TILE_W;
        const int cc = idx - r * TILE_W;
        const int gy = reflect_idx(y0 - 3 + r, IMG_H);
        const int gx = reflect_idx(x0 - 3 + cc, IMG_W);
        const float v = fmaf(plane[gy * IMG_W + gx], sd, mean);
        tile[r][cc] = fminf(fmaxf(v, 0.0f), 1.0f);
    }
    __syncthreads();

    // ---- Phase 2: sort every column of every row-window once; store sorted ----
#pragma unroll
    for (int k = 0; k < 5; ++k) {
        const int col = tx + 32 * k;
        if (col < TILE_W) {
            float v[7];
#pragma unroll
            for (int i = 0; i < 7; ++i) v[i] = tile[ty + i][col];
            apply_col<0>(v);
            store_sorted<0>(v, scol, ty, col);
        }
    }
    __syncthreads();

    // ---- Phase 3: 4 outputs per thread, strided by 32 (conflict-free LDS) ----
#pragma unroll
    for (int o = 0; o < WOUT; ++o) {
        const int base = tx + 32 * o;       // window's leftmost local column
        float w[49];
#pragma unroll
        for (int r = 0; r < 7; ++r)
#pragma unroll
            for (int j = 0; j < 7; ++j)
                w[7 * r + j] = scol[r][ty][base + j];

        apply_sel<0>(w);

        float t[12];
        t[0] = w[sel::F14];
        rank_terms<1>(t, w);
#pragma unroll
        for (int k = 0; k < 6; ++k) t[k] = fminf(t[k], t[k + 6]);
#pragma unroll
        for (int k = 0; k < 3; ++k) t[k] = fminf(t[k], t[k + 3]);
        const float med = fminf(t[0], fminf(t[1], t[2]));

        out[(size_t)bc * PLANE_ELEMS + (size_t)(y0 + ty) * IMG_W + (x0 + base)] =
            (med - mean) * inv_sd;
    }
}

extern "C" void kernel_launch(void* const* d_in, const int* in_sizes, int n_in,
                              void* d_out, int out_size) {
    const float* img  = (const float*)d_in[0];
    const float* mask = (const float*)d_in[1];
    float* out = (float*)d_out;

    dim3 block(BX, BY, 1);
    dim3 grid(IMG_W / OUTW, IMG_H / BY, N_PLANES);   // 4 x 64 x 24
    median7_kernel<<<grid, block>>>(img, out);

    cudaMemcpyAsync(out + IMG_ELEMS, mask, (size_t)MASK_ELEMS * sizeof(float),
                    cudaMemcpyDeviceToDevice);
}

// round 9
// speedup vs baseline: 3.2013x; 1.0402x over previous
#include <cuda_runtime.h>
#include <cstddef>

// MedianFilter 7x7, exact-order-statistic, fp32. Sorted columns staged in
// shared memory; per-output both-sorted-matrix selection network; and
// MIXED-PIPE compare-exchange: a compile-time fraction of comparators is
// lowered to FADD/FMUL arithmetic (fma pipe) instead of FMNMX (alu pipe)
// so both SM pipes run concurrently.
// img:  [8,3,512,512] fp32   mask: [8,1,512,512] fp32
// out = concat( normalize(median7x7(clip(unnormalize(img),0,1))), mask )

#define IMG_H 512
#define IMG_W 512
#define N_PLANES 24
#define PLANE_ELEMS (IMG_H * IMG_W)
#define IMG_ELEMS (N_PLANES * PLANE_ELEMS)
#define MASK_ELEMS (8 * PLANE_ELEMS)

#define BX 32
#define BY 8
#define WOUT 4
#define OUTW (BX * WOUT)          // 128 outputs per block in x
#define TILE_W (OUTW + 6)         // 134
#define TILE_H (BY + 6)           // 14
#define TPITCH 136

// Fraction of comparators routed to the fma pipe: (K & FMA_MASK) == FMA_PICK.
// f = 1/4 predicted balance for ~12-cycle fma-CE vs 4-cycle alu-CE.
#define FMA_MASK 3
#define FMA_PICK 1

// ============================================================
// Compile-time Batcher odd-even merge network generator
// ============================================================
namespace sel {

template <int CAP> struct NetT {
    short a[CAP] = {};
    short b[CAP] = {};
    int n = 0;
};

template <int CAP>
constexpr void net_add(NetT<CAP>& net, int x, int y) {
    net.a[net.n] = (short)x;
    net.b[net.n] = (short)y;
    net.n++;
}

// Batcher odd-even merge of sorted index lists A(m), B(n).
// Appends comparators to net; writes the sorted READ ORDER (m+n indices) to out.
template <int CAP>
constexpr void gen_merge(const short* A, int m, const short* B, int n,
                         short* out, NetT<CAP>& net) {
    if (m == 0) { for (int i = 0; i < n; ++i) out[i] = B[i]; return; }
    if (n == 0) { for (int i = 0; i < m; ++i) out[i] = A[i]; return; }
    if (m == 1 && n == 1) {
        net_add(net, A[0], B[0]);
        out[0] = A[0]; out[1] = B[0];
        return;
    }
    short Ae[10] = {}, Ao[10] = {}, Be[10] = {}, Bo[10] = {};
    int mae = 0, mao = 0, nbe = 0, nbo = 0;
    for (int i = 0; i < m; ++i) { if ((i & 1) == 0) Ae[mae++] = A[i]; else Ao[mao++] = A[i]; }
    for (int i = 0; i < n; ++i) { if ((i & 1) == 0) Be[nbe++] = B[i]; else Bo[nbo++] = B[i]; }
    short V[20] = {}, W[20] = {};
    gen_merge(Ae, mae, Be, nbe, V, net);
    gen_merge(Ao, mao, Bo, nbo, W, net);
    const int nv = mae + nbe, nw = mao + nbo;
    int oi = 0;
    out[oi++] = V[0];
    int i = 0;
    for (; i < nw && i + 1 < nv; ++i) {
        net_add(net, W[i], V[i + 1]);     // min stays at W[i], max at V[i+1]
        out[oi++] = W[i];
        out[oi++] = V[i + 1];
    }
    for (int j = i; j < nw; ++j) out[oi++] = W[j];
    for (int j = i + 1; j < nv; ++j) out[oi++] = V[j];
}

template <int CAP>
constexpr void gen_sort(const short* idx, int len, short* out, NetT<CAP>& net) {
    if (len == 1) { out[0] = idx[0]; return; }
    const int h = len / 2;
    short L[8] = {}, R[8] = {}, SL[8] = {}, SR[8] = {};
    for (int i = 0; i < h; ++i) L[i] = idx[i];
    for (int i = h; i < len; ++i) R[i - h] = idx[i];
    gen_sort(L, h, SL, net);
    gen_sort(R, len - h, SR, net);
    gen_merge(SL, h, SR, len - h, out, net);
}

struct Plan {
    NetT<24>  colnet;        // sort network on one 7-element column (indices 0..6)
    short     cperm[7] = {}; // read order: column[cperm[i]] = i-th smallest
    NetT<224> selnet;        // per-output network on w[49]
    short     E[11] = {};    // sorted read order, 11-list
    short     F[18] = {};    // sorted read order, 18-list
};

constexpr Plan make_plan() {
    Plan p{};
    short base[7] = {0, 1, 2, 3, 4, 5, 6};
    gen_sort(base, 7, p.cperm, p.colnet);

    // Row sorts over w[49]; w[7r+j] = j-th window column's r-th smallest.
    short rowperm[7][7] = {};
    for (int r = 0; r < 7; ++r) {
        short idx[7] = {}, outp[7] = {};
        for (int j = 0; j < 7; ++j) idx[j] = (short)(7 * r + j);
        gen_sort(idx, 7, outp, p.selnet);
        for (int j = 0; j < 7; ++j) rowperm[r][j] = outp[j];
    }

    // Candidate chains in the both-sorted matrix: cell (r,k) is a median
    // candidate iff (r+1)(k+1) <= 25 and (7-r)(7-k) <= 25.
    short R0[3] = {}, R1[4] = {}, R2[5] = {}, R3[5] = {}, R4[5] = {}, R5[4] = {}, R6[3] = {};
    for (int j = 0; j < 3; ++j) R0[j] = rowperm[0][4 + j];
    for (int j = 0; j < 4; ++j) R1[j] = rowperm[1][3 + j];
    for (int j = 0; j < 5; ++j) R2[j] = rowperm[2][2 + j];
    for (int j = 0; j < 5; ++j) R3[j] = rowperm[3][1 + j];
    for (int j = 0; j < 5; ++j) R4[j] = rowperm[4][0 + j];
    for (int j = 0; j < 4; ++j) R5[j] = rowperm[5][0 + j];
    for (int j = 0; j < 3; ++j) R6[j] = rowperm[6][0 + j];

    short A6[6] = {}, B8[8] = {}, C10[10] = {}, E11[11] = {}, F18[18] = {};
    gen_merge(R0, 3, R6, 3, A6, p.selnet);
    gen_merge(R1, 4, R5, 4, B8, p.selnet);
    gen_merge(R2, 5, R4, 5, C10, p.selnet);
    gen_merge(A6, 6, R3, 5, E11, p.selnet);
    gen_merge(B8, 8, C10, 10, F18, p.selnet);
    for (int i = 0; i < 11; ++i) p.E[i] = E11[i];
    for (int i = 0; i < 18; ++i) p.F[i] = F18[i];
    return p;
}

constexpr Plan PLAN = make_plan();

static_assert(PLAN.colnet.n <= 24, "colnet overflow");
static_assert(PLAN.selnet.n <= 224, "selnet overflow");

// Integral constexpr: folds to an immediate in device code.
constexpr int F14 = PLAN.F[14];

// ---- compile-time verification ----

constexpr bool check_sort7() {
    for (int mask = 0; mask < 128; ++mask) {
        int v[7] = {};
        for (int i = 0; i < 7; ++i) v[i] = (mask >> i) & 1;
        for (int k = 0; k < PLAN.colnet.n; ++k) {
            const int x = v[PLAN.colnet.a[k]], y = v[PLAN.colnet.b[k]];
            v[PLAN.colnet.a[k]] = x < y ? x : y;
            v[PLAN.colnet.b[k]] = x < y ? y : x;
        }
        for (int i = 0; i + 1 < 7; ++i)
            if (v[PLAN.cperm[i]] > v[PLAN.cperm[i + 1]]) return false;
    }
    return true;
}
static_assert(check_sort7(), "sort7 network invalid");

// 0/1 principle on both-sorted inputs; circuit is monotone, so boundary
// totals 24 (->0) and 25 (->1) prove correctness for all inputs.
constexpr bool check_select() {
    for (int h0 = 0; h0 <= 7; ++h0)
    for (int h1 = h0; h1 <= 7; ++h1)
    for (int h2 = h1; h2 <= 7; ++h2)
    for (int h3 = h2; h3 <= 7; ++h3)
    for (int h4 = h3; h4 <= 7; ++h4)
    for (int h5 = h4; h5 <= 7; ++h5)
    for (int h6 = h5; h6 <= 7; ++h6) {
        const int tot = h0 + h1 + h2 + h3 + h4 + h5 + h6;
        if (tot != 24 && tot != 25) continue;
        const int h[7] = {h0, h1, h2, h3, h4, h5, h6};
        int w[49] = {};
        for (int r = 0; r < 7; ++r)
            for (int c = 0; c < 7; ++c)
                w[7 * r + c] = (r >= 7 - h[c]) ? 1 : 0;
        for (int k = 0; k < PLAN.selnet.n; ++k) {
            const int x = w[PLAN.selnet.a[k]], y = w[PLAN.selnet.b[k]];
            w[PLAN.selnet.a[k]] = x < y ? x : y;
            w[PLAN.selnet.b[k]] = x < y ? y : x;
        }
        int res = w[F14];
        for (int i = 1; i <= 11; ++i) {
            const int t1 = w[PLAN.E[i - 1]], t2 = w[PLAN.F[14 - i]];
            const int mx = t1 > t2 ? t1 : t2;
            res = res < mx ? res : mx;
        }
        if (res != (tot >= 25 ? 1 : 0)) return false;
    }
    return true;
}
static_assert(check_select(), "median selection network invalid");

}  // namespace sel

// ============================================================
// Device side
// ============================================================

// alu-pipe compare-exchange: 2x FMNMX.
__device__ __forceinline__ void ce(float& x, float& y) {
    const float lo = fminf(x, y);
    y = fmaxf(x, y);
    x = lo;
}

// fma-pipe compare-exchange: min/max via sum/abs-diff identity.
// Inputs are in [0,1]; adds <= ~3 ulp rounding error (tolerance is 1e-3).
__device__ __forceinline__ void ce_fma(float& x, float& y) {
    const float s  = x + y;
    const float d  = x - y;
    const float ad = fabsf(d);
    x = (s - ad) * 0.5f;
    y = (s + ad) * 0.5f;
}

template <int K>
__device__ __forceinline__ void apply_col(float (&v)[7]) {
    if constexpr (K < sel::PLAN.colnet.n) {
        constexpr int ia = sel::PLAN.colnet.a[K];
        constexpr int ib = sel::PLAN.colnet.b[K];
        if constexpr ((K & FMA_MASK) == FMA_PICK) ce_fma(v[ia], v[ib]);
        else                                      ce(v[ia], v[ib]);
        apply_col<K + 1>(v);
    }
}

template <int K>
__device__ __forceinline__ void apply_sel(float (&w)[49]) {
    if constexpr (K < sel::PLAN.selnet.n) {
        constexpr int ia = sel::PLAN.selnet.a[K];
        constexpr int ib = sel::PLAN.selnet.b[K];
        if constexpr ((K & FMA_MASK) == FMA_PICK) ce_fma(w[ia], w[ib]);
        else                                      ce(w[ia], w[ib]);
        apply_sel<K + 1>(w);
    }
}

template <int I>
__device__ __forceinline__ void rank_terms(float (&t)[12], const float (&w)[49]) {
    if constexpr (I <= 11) {
        constexpr int e = sel::PLAN.E[I - 1];
        constexpr int f = sel::PLAN.F[14 - I];
        t[I] = fmaxf(w[e], w[f]);
        rank_terms<I + 1>(t, w);
    }
}

// Store sorted column to shared in rank order; cperm index made constexpr.
template <int R>
__device__ __forceinline__ void store_sorted(const float (&v)[7],
                                             float (*scol)[BY][TPITCH],
                                             int ty, int col) {
    if constexpr (R < 7) {
        constexpr int cp = sel::PLAN.cperm[R];
        scol[R][ty][col] = v[cp];
        store_sorted<R + 1>(v, scol, ty, col);
    }
}

__device__ __forceinline__ int reflect_idx(int g, int n) {
    g = (g < 0) ? -g : g;
    g = (g >= n) ? (2 * n - 2 - g) : g;
    return g;
}

__global__ void __launch_bounds__(BX * BY, 3)
median7_kernel(const float* __restrict__ img, float* __restrict__ out) {
    __shared__ float tile[TILE_H][TPITCH];           // 7.6 KB
    __shared__ float scol[7][BY][TPITCH];            // 30.5 KB: sorted columns

    const int bc = blockIdx.z;
    const int ch = bc % 3;
    const float mean   = (ch == 0) ? 0.485f : (ch == 1) ? 0.456f : 0.406f;
    const float sd     = (ch == 0) ? 0.229f : (ch == 1) ? 0.224f : 0.225f;
    const float inv_sd = (ch == 0) ? (1.0f / 0.229f) : (ch == 1) ? (1.0f / 0.224f) : (1.0f / 0.225f);

    const int x0 = blockIdx.x * OUTW;
    const int y0 = blockIdx.y * BY;
    const float* __restrict__ plane = img + (size_t)bc * PLANE_ELEMS;

    const int tx = threadIdx.x;
    const int ty = threadIdx.y;
    const int tid = ty * BX + tx;

    // ---- Phase 1: load + unnormalize + clip into shared tile ----
    for (int idx = tid; idx < TILE_H * TILE_W; idx += BX * BY) {
        const int r  = idx / TILE_W;
        const int cc = idx - r * TILE_W;
        const int gy = reflect_idx(y0 - 3 + r, IMG_H);
        const int gx = reflect_idx(x0 - 3 + cc, IMG_W);
        const float v = fmaf(plane[gy * IMG_W + gx], sd, mean);
        tile[r][cc] = fminf(fmaxf(v, 0.0f), 1.0f);
    }
    __syncthreads();

    // ---- Phase 2: sort every column of every row-window once; store sorted ----
#pragma unroll
    for (int k = 0; k < 5; ++k) {
        const int col = tx + 32 * k;
        if (col < TILE_W) {
            float v[7];
#pragma unroll
            for (int i = 0; i < 7; ++i) v[i] = tile[ty + i][col];
            apply_col<0>(v);
            store_sorted<0>(v, scol, ty, col);
        }
    }
    __syncthreads();

    // ---- Phase 3: 4 outputs per thread, strided by 32 (conflict-free LDS) ----
#pragma unroll
    for (int o = 0; o < WOUT; ++o) {
        const int base = tx + 32 * o;       // window's leftmost local column
        float w[49];
#pragma unroll
        for (int r = 0; r < 7; ++r)
#pragma unroll
            for (int j = 0; j < 7; ++j)
                w[7 * r + j] = scol[r][ty][base + j];

        apply_sel<0>(w);

        float t[12];
        t[0] = w[sel::F14];
        rank_terms<1>(t, w);
#pragma unroll
        for (int k = 0; k < 6; ++k) t[k] = fminf(t[k], t[k + 6]);
#pragma unroll
        for (int k = 0; k < 3; ++k) t[k] = fminf(t[k], t[k + 3]);
        const float med = fminf(t[0], fminf(t[1], t[2]));

        out[(size_t)bc * PLANE_ELEMS + (size_t)(y0 + ty) * IMG_W + (x0 + base)] =
            (med - mean) * inv_sd;
    }
}

extern "C" void kernel_launch(void* const* d_in, const int* in_sizes, int n_in,
                              void* d_out, int out_size) {
    const float* img  = (const float*)d_in[0];
    const float* mask = (const float*)d_in[1];
    float* out = (float*)d_out;

    dim3 block(BX, BY, 1);
    dim3 grid(IMG_W / OUTW, IMG_H / BY, N_PLANES);   // 4 x 64 x 24
    median7_kernel<<<grid, block>>>(img, out);

    cudaMemcpyAsync(out + IMG_ELEMS, mask, (size_t)MASK_ELEMS * sizeof(float),
                    cudaMemcpyDeviceToDevice);
}

// round 11
// speedup vs baseline: 3.4165x; 1.0672x over previous
#include <cuda_runtime.h>
#include <cstddef>

// MedianFilter 7x7, exact-order-statistic, fp32. Sorted columns staged in
// shared memory; per-output both-sorted-matrix selection network; and
// TWO-PIPE compare-exchange: half the comparators use a 3-instruction
// min+reconstruct-max form (FMNMX on alu pipe + 2 FFMA on fma pipe), the
// other half stay as 2x FMNMX, so alu and fma pipes run concurrently with
// minimal issue-slot overhead.
// img:  [8,3,512,512] fp32   mask: [8,1,512,512] fp32
// out = concat( normalize(median7x7(clip(unnormalize(img),0,1))), mask )

#define IMG_H 512
#define IMG_W 512
#define N_PLANES 24
#define PLANE_ELEMS (IMG_H * IMG_W)
#define IMG_ELEMS (N_PLANES * PLANE_ELEMS)
#define MASK_ELEMS (8 * PLANE_ELEMS)

#define BX 32
#define BY 8
#define WOUT 4
#define OUTW (BX * WOUT)          // 128 outputs per block in x
#define TILE_W (OUTW + 6)         // 134
#define TILE_H (BY + 6)           // 14
#define TPITCH 136

// Comparators with (K & FMA_MASK) == FMA_PICK use the two-pipe 3-instr CE.
// g = 1/2 predicted optimum from the issue/alu/fma cost model.
#define FMA_MASK 1
#define FMA_PICK 0

// ============================================================
// Compile-time Batcher odd-even merge network generator
// ============================================================
namespace sel {

template <int CAP> struct NetT {
    short a[CAP] = {};
    short b[CAP] = {};
    int n = 0;
};

template <int CAP>
constexpr void net_add(NetT<CAP>& net, int x, int y) {
    net.a[net.n] = (short)x;
    net.b[net.n] = (short)y;
    net.n++;
}

// Batcher odd-even merge of sorted index lists A(m), B(n).
// Appends comparators to net; writes the sorted READ ORDER (m+n indices) to out.
template <int CAP>
constexpr void gen_merge(const short* A, int m, const short* B, int n,
                         short* out, NetT<CAP>& net) {
    if (m == 0) { for (int i = 0; i < n; ++i) out[i] = B[i]; return; }
    if (n == 0) { for (int i = 0; i < m; ++i) out[i] = A[i]; return; }
    if (m == 1 && n == 1) {
        net_add(net, A[0], B[0]);
        out[0] = A[0]; out[1] = B[0];
        return;
    }
    short Ae[10] = {}, Ao[10] = {}, Be[10] = {}, Bo[10] = {};
    int mae = 0, mao = 0, nbe = 0, nbo = 0;
    for (int i = 0; i < m; ++i) { if ((i & 1) == 0) Ae[mae++] = A[i]; else Ao[mao++] = A[i]; }
    for (int i = 0; i < n; ++i) { if ((i & 1) == 0) Be[nbe++] = B[i]; else Bo[nbo++] = B[i]; }
    short V[20] = {}, W[20] = {};
    gen_merge(Ae, mae, Be, nbe, V, net);
    gen_merge(Ao, mao, Bo, nbo, W, net);
    const int nv = mae + nbe, nw = mao + nbo;
    int oi = 0;
    out[oi++] = V[0];
    int i = 0;
    for (; i < nw && i + 1 < nv; ++i) {
        net_add(net, W[i], V[i + 1]);     // min stays at W[i], max at V[i+1]
        out[oi++] = W[i];
        out[oi++] = V[i + 1];
    }
    for (int j = i; j < nw; ++j) out[oi++] = W[j];
    for (int j = i + 1; j < nv; ++j) out[oi++] = V[j];
}

template <int CAP>
constexpr void gen_sort(const short* idx, int len, short* out, NetT<CAP>& net) {
    if (len == 1) { out[0] = idx[0]; return; }
    const int h = len / 2;
    short L[8] = {}, R[8] = {}, SL[8] = {}, SR[8] = {};
    for (int i = 0; i < h; ++i) L[i] = idx[i];
    for (int i = h; i < len; ++i) R[i - h] = idx[i];
    gen_sort(L, h, SL, net);
    gen_sort(R, len - h, SR, net);
    gen_merge(SL, h, SR, len - h, out, net);
}

struct Plan {
    NetT<24>  colnet;        // sort network on one 7-element column (indices 0..6)
    short     cperm[7] = {}; // read order: column[cperm[i]] = i-th smallest
    NetT<224> selnet;        // per-output network on w[49]
    short     E[11] = {};    // sorted read order, 11-list
    short     F[18] = {};    // sorted read order, 18-list
};

constexpr Plan make_plan() {
    Plan p{};
    short base[7] = {0, 1, 2, 3, 4, 5, 6};
    gen_sort(base, 7, p.cperm, p.colnet);

    // Row sorts over w[49]; w[7r+j] = j-th window column's r-th smallest.
    short rowperm[7][7] = {};
    for (int r = 0; r < 7; ++r) {
        short idx[7] = {}, outp[7] = {};
        for (int j = 0; j < 7; ++j) idx[j] = (short)(7 * r + j);
        gen_sort(idx, 7, outp, p.selnet);
        for (int j = 0; j < 7; ++j) rowperm[r][j] = outp[j];
    }

    // Candidate chains in the both-sorted matrix: cell (r,k) is a median
    // candidate iff (r+1)(k+1) <= 25 and (7-r)(7-k) <= 25.
    short R0[3] = {}, R1[4] = {}, R2[5] = {}, R3[5] = {}, R4[5] = {}, R5[4] = {}, R6[3] = {};
    for (int j = 0; j < 3; ++j) R0[j] = rowperm[0][4 + j];
    for (int j = 0; j < 4; ++j) R1[j] = rowperm[1][3 + j];
    for (int j = 0; j < 5; ++j) R2[j] = rowperm[2][2 + j];
    for (int j = 0; j < 5; ++j) R3[j] = rowperm[3][1 + j];
    for (int j = 0; j < 5; ++j) R4[j] = rowperm[4][0 + j];
    for (int j = 0; j < 4; ++j) R5[j] = rowperm[5][0 + j];
    for (int j = 0; j < 3; ++j) R6[j] = rowperm[6][0 + j];

    short A6[6] = {}, B8[8] = {}, C10[10] = {}, E11[11] = {}, F18[18] = {};
    gen_merge(R0, 3, R6, 3, A6, p.selnet);
    gen_merge(R1, 4, R5, 4, B8, p.selnet);
    gen_merge(R2, 5, R4, 5, C10, p.selnet);
    gen_merge(A6, 6, R3, 5, E11, p.selnet);
    gen_merge(B8, 8, C10, 10, F18, p.selnet);
    for (int i = 0; i < 11; ++i) p.E[i] = E11[i];
    for (int i = 0; i < 18; ++i) p.F[i] = F18[i];
    return p;
}

constexpr Plan PLAN = make_plan();

static_assert(PLAN.colnet.n <= 24, "colnet overflow");
static_assert(PLAN.selnet.n <= 224, "selnet overflow");

// Integral constexpr: folds to an immediate in device code.
constexpr int F14 = PLAN.F[14];

// ---- compile-time verification ----

constexpr bool check_sort7() {
    for (int mask = 0; mask < 128; ++mask) {
        int v[7] = {};
        for (int i = 0; i < 7; ++i) v[i] = (mask >> i) & 1;
        for (int k = 0; k < PLAN.colnet.n; ++k) {
            const int x = v[PLAN.colnet.a[k]], y = v[PLAN.colnet.b[k]];
            v[PLAN.colnet.a[k]] = x < y ? x : y;
            v[PLAN.colnet.b[k]] = x < y ? y : x;
        }
        for (int i = 0; i + 1 < 7; ++i)
            if (v[PLAN.cperm[i]] > v[PLAN.cperm[i + 1]]) return false;
    }
    return true;
}
static_assert(check_sort7(), "sort7 network invalid");

// 0/1 principle on both-sorted inputs; circuit is monotone, so boundary
// totals 24 (->0) and 25 (->1) prove correctness for all inputs.
constexpr bool check_select() {
    for (int h0 = 0; h0 <= 7; ++h0)
    for (int h1 = h0; h1 <= 7; ++h1)
    for (int h2 = h1; h2 <= 7; ++h2)
    for (int h3 = h2; h3 <= 7; ++h3)
    for (int h4 = h3; h4 <= 7; ++h4)
    for (int h5 = h4; h5 <= 7; ++h5)
    for (int h6 = h5; h6 <= 7; ++h6) {
        const int tot = h0 + h1 + h2 + h3 + h4 + h5 + h6;
        if (tot != 24 && tot != 25) continue;
        const int h[7] = {h0, h1, h2, h3, h4, h5, h6};
        int w[49] = {};
        for (int r = 0; r < 7; ++r)
            for (int c = 0; c < 7; ++c)
                w[7 * r + c] = (r >= 7 - h[c]) ? 1 : 0;
        for (int k = 0; k < PLAN.selnet.n; ++k) {
            const int x = w[PLAN.selnet.a[k]], y = w[PLAN.selnet.b[k]];
            w[PLAN.selnet.a[k]] = x < y ? x : y;
            w[PLAN.selnet.b[k]] = x < y ? y : x;
        }
        int res = w[F14];
        for (int i = 1; i <= 11; ++i) {
            const int t1 = w[PLAN.E[i - 1]], t2 = w[PLAN.F[14 - i]];
            const int mx = t1 > t2 ? t1 : t2;
            res = res < mx ? res : mx;
        }
        if (res != (tot >= 25 ? 1 : 0)) return false;
    }
    return true;
}
static_assert(check_select(), "median selection network invalid");

}  // namespace sel

// ============================================================
// Device side
// ============================================================

// alu-pipe compare-exchange: 2x FMNMX.
__device__ __forceinline__ void ce(float& x, float& y) {
    const float lo = fminf(x, y);
    y = fmaxf(x, y);
    x = lo;
}

// Two-pipe 3-instruction CE: FMNMX (alu) + 2 FFMA-imm (fma pipe).
// max reconstructed as (x+y) - min: within ~1 ulp of exact (inputs in [0,1]),
// accumulated error << the 1e-3 tolerance.
__device__ __forceinline__ void ce_b(float& x, float& y) {
    const float s  = __fmaf_rn(x, 1.0f, y);   // fma pipe (FFMA-imm)
    const float mn = fminf(x, y);             // alu pipe (FMNMX)
    y = __fmaf_rn(mn, -1.0f, s);              // fma pipe: s - mn = max
    x = mn;
}

template <int K>
__device__ __forceinline__ void apply_col(float (&v)[7]) {
    if constexpr (K < sel::PLAN.colnet.n) {
        constexpr int ia = sel::PLAN.colnet.a[K];
        constexpr int ib = sel::PLAN.colnet.b[K];
        if constexpr ((K & FMA_MASK) == FMA_PICK) ce_b(v[ia], v[ib]);
        else                                      ce(v[ia], v[ib]);
        apply_col<K + 1>(v);
    }
}

template <int K>
__device__ __forceinline__ void apply_sel(float (&w)[49]) {
    if constexpr (K < sel::PLAN.selnet.n) {
        constexpr int ia = sel::PLAN.selnet.a[K];
        constexpr int ib = sel::PLAN.selnet.b[K];
        if constexpr ((K & FMA_MASK) == FMA_PICK) ce_b(w[ia], w[ib]);
        else                                      ce(w[ia], w[ib]);
        apply_sel<K + 1>(w);
    }
}

template <int I>
__device__ __forceinline__ void rank_terms(float (&t)[12], const float (&w)[49]) {
    if constexpr (I <= 11) {
        constexpr int e = sel::PLAN.E[I - 1];
        constexpr int f = sel::PLAN.F[14 - I];
        t[I] = fmaxf(w[e], w[f]);
        rank_terms<I + 1>(t, w);
    }
}

// Store sorted column to shared in rank order; cperm index made constexpr.
template <int R>
__device__ __forceinline__ void store_sorted(const float (&v)[7],
                                             float (*scol)[BY][TPITCH],
                                             int ty, int col) {
    if constexpr (R < 7) {
        constexpr int cp = sel::PLAN.cperm[R];
        scol[R][ty][col] = v[cp];
        store_sorted<R + 1>(v, scol, ty, col);
    }
}

__device__ __forceinline__ int reflect_idx(int g, int n) {
    g = (g < 0) ? -g : g;
    g = (g >= n) ? (2 * n - 2 - g) : g;
    return g;
}

__global__ void __launch_bounds__(BX * BY, 3)
median7_kernel(const float* __restrict__ img, float* __restrict__ out) {
    __shared__ float tile[TILE_H][TPITCH];           // 7.6 KB
    __shared__ float scol[7][BY][TPITCH];            // 30.5 KB: sorted columns

    const int bc = blockIdx.z;
    const int ch = bc % 3;
    const float mean   = (ch == 0) ? 0.485f : (ch == 1) ? 0.456f : 0.406f;
    const float sd     = (ch == 0) ? 0.229f : (ch == 1) ? 0.224f : 0.225f;
    const float inv_sd = (ch == 0) ? (1.0f / 0.229f) : (ch == 1) ? (1.0f / 0.224f) : (1.0f / 0.225f);

    const int x0 = blockIdx.x * OUTW;
    const int y0 = blockIdx.y * BY;
    const float* __restrict__ plane = img + (size_t)bc * PLANE_ELEMS;

    const int tx = threadIdx.x;
    const int ty = threadIdx.y;
    const int tid = ty * BX + tx;

    // ---- Phase 1: load + unnormalize + clip into shared tile ----
    for (int idx = tid; idx < TILE_H * TILE_W; idx += BX * BY) {
        const int r  = idx / TILE_W;
        const int cc = idx - r * TILE_W;
        const int gy = reflect_idx(y0 - 3 + r, IMG_H);
        const int gx = reflect_idx(x0 - 3 + cc, IMG_W);
        const float v = fmaf(plane[gy * IMG_W + gx], sd, mean);
        tile[r][cc] = fminf(fmaxf(v, 0.0f), 1.0f);
    }
    __syncthreads();

    // ---- Phase 2: sort every column of every row-window once; store sorted ----
#pragma unroll
    for (int k = 0; k < 5; ++k) {
        const int col = tx + 32 * k;
        if (col < TILE_W) {
            float v[7];
#pragma unroll
            for (int i = 0; i < 7; ++i) v[i] = tile[ty + i][col];
            apply_col<0>(v);
            store_sorted<0>(v, scol, ty, col);
        }
    }
    __syncthreads();

    // ---- Phase 3: 4 outputs per thread, strided by 32 (conflict-free LDS) ----
#pragma unroll
    for (int o = 0; o < WOUT; ++o) {
        const int base = tx + 32 * o;       // window's leftmost local column
        float w[49];
#pragma unroll
        for (int r = 0; r < 7; ++r)
#pragma unroll
            for (int j = 0; j < 7; ++j)
                w[7 * r + j] = scol[r][ty][base + j];

        apply_sel<0>(w);

        float t[12];
        t[0] = w[sel::F14];
        rank_terms<1>(t, w);
#pragma unroll
        for (int k = 0; k < 6; ++k) t[k] = fminf(t[k], t[k + 6]);
#pragma unroll
        for (int k = 0; k < 3; ++k) t[k] = fminf(t[k], t[k + 3]);
        const float med = fminf(t[0], fminf(t[1], t[2]));

        out[(size_t)bc * PLANE_ELEMS + (size_t)(y0 + ty) * IMG_W + (x0 + base)] =
            (med - mean) * inv_sd;
    }
}

extern "C" void kernel_launch(void* const* d_in, const int* in_sizes, int n_in,
                              void* d_out, int out_size) {
    const float* img  = (const float*)d_in[0];
    const float* mask = (const float*)d_in[1];
    float* out = (float*)d_out;

    dim3 block(BX, BY, 1);
    dim3 grid(IMG_W / OUTW, IMG_H / BY, N_PLANES);   // 4 x 64 x 24
    median7_kernel<<<grid, block>>>(img, out);

    cudaMemcpyAsync(out + IMG_ELEMS, mask, (size_t)MASK_ELEMS * sizeof(float),
                    cudaMemcpyDeviceToDevice);
}